// round 14
// baseline (speedup 1.0000x reference)
#include <cuda_runtime.h>
#include <cuda_fp16.h>
#include <cstdint>

#define S_SZ 2048
#define D_SZ 1024
#define H_SZ 16
#define HD_SZ 64
#define B_SZ 2
#define BH_SZ (B_SZ * H_SZ)       // 32
#define TOK_SZ (B_SZ * S_SZ)      // 4096
#define KLOG 0.18033688011112042f // 0.125 * log2(e)
#define KSTR 72                   // halves per smem row (144B: LDSM conflict-free)

// Scratch (device globals: allocation-free rule)
__device__ __half g_Xh[TOK_SZ * D_SZ];        // fp16 X, natural order
__device__ __half g_Wh[3 * D_SZ * D_SZ];      // fp16 W^T [n][k]; Wq pre-scaled by KLOG
__device__ __half g_Qh[BH_SZ * S_SZ * HD_SZ]; // fp16 Q (KLOG-scaled), natural d
__device__ __half g_Kh[BH_SZ * S_SZ * HD_SZ]; // fp16 K, natural d
__device__ float  g_V[BH_SZ * S_SZ * HD_SZ];  // full fp32
__device__ float  g_Ri[BH_SZ * S_SZ];         // 1 / rowsum(exp2(scores2))
__device__ float  g_w[BH_SZ * S_SZ];          // mean attention weight per key

// ---------------------------------------------------------------------------
__device__ __forceinline__ void mma16h(float c[4], const unsigned a[4], const unsigned* b) {
    asm volatile(
        "mma.sync.aligned.m16n8k16.row.col.f32.f16.f16.f32 "
        "{%0,%1,%2,%3}, {%4,%5,%6,%7}, {%8,%9}, {%0,%1,%2,%3};\n"
        : "+f"(c[0]), "+f"(c[1]), "+f"(c[2]), "+f"(c[3])
        : "r"(a[0]), "r"(a[1]), "r"(a[2]), "r"(a[3]), "r"(b[0]), "r"(b[1]));
}

__device__ __forceinline__ void ldsm4(unsigned& r0, unsigned& r1, unsigned& r2, unsigned& r3,
                                      uint32_t addr) {
    asm volatile("ldmatrix.sync.aligned.m8n8.x4.shared.b16 {%0,%1,%2,%3}, [%4];"
                 : "=r"(r0), "=r"(r1), "=r"(r2), "=r"(r3) : "r"(addr));
}

// two exp2 per MUFU op
__device__ __forceinline__ __half2 h2ex2(__half2 x) {
    unsigned xi = *reinterpret_cast<unsigned*>(&x), yi;
    asm("ex2.approx.f16x2 %0, %1;" : "=r"(yi) : "r"(xi));
    return *reinterpret_cast<__half2*>(&yi);
}

__device__ __forceinline__ void cpa16(uint32_t dst, const void* src) {
    asm volatile("cp.async.ca.shared.global [%0], [%1], 16;\n" :: "r"(dst), "l"(src));
}
__device__ __forceinline__ void cp_commit() { asm volatile("cp.async.commit_group;\n"); }
template <int N> __device__ __forceinline__ void cp_wait() {
    asm volatile("cp.async.wait_group %0;\n" :: "n"(N));
}

// ---------------------------------------------------------------------------
// Prep (fused): blocks [0,1024) convert X to fp16; blocks [1024,4096) build
// fp16 W^T with KLOG folded into Wq.
// ---------------------------------------------------------------------------
__global__ __launch_bounds__(256) void prep_all(const float* __restrict__ X,
                                                const float* __restrict__ Wq,
                                                const float* __restrict__ Wk,
                                                const float* __restrict__ Wv) {
    __shared__ float s[32][33];
    const int bx = blockIdx.x, tid = threadIdx.x;
    if (bx < 1024) {
        const int N8 = TOK_SZ * D_SZ / 8;
        for (int i = bx * 256 + tid; i < N8; i += 1024 * 256) {
            float4 v0 = ((const float4*)X)[2 * i];
            float4 v1 = ((const float4*)X)[2 * i + 1];
            __half2 h[4] = { __floats2half2_rn(v0.x, v0.y), __floats2half2_rn(v0.z, v0.w),
                             __floats2half2_rn(v1.x, v1.y), __floats2half2_rn(v1.z, v1.w) };
            *(uint4*)(g_Xh + (size_t)8 * i) = *(const uint4*)h;
        }
        return;
    }
    const int idx = bx - 1024;
    const int sel = idx >> 10, rem = idx & 1023;
    const int k0 = (rem & 31) * 32, n0 = (rem >> 5) * 32;
    const float* Wp = (sel == 0) ? Wq : (sel == 1) ? Wk : Wv;
    const float scale = (sel == 0) ? KLOG : 1.0f;
    const int tx = tid & 31, ty = tid >> 5;

    #pragma unroll
    for (int j = 0; j < 4; j++) {
        int kr = ty + j * 8;
        s[kr][tx] = Wp[(size_t)(k0 + kr) * D_SZ + n0 + tx] * scale;
    }
    __syncthreads();

    __half* outp = g_Wh + (size_t)sel * D_SZ * D_SZ;
    #pragma unroll
    for (int j = 0; j < 2; j++) {
        int i2 = tid + 256 * j;
        int nc = i2 >> 4, pe = (i2 & 15) << 1;
        __half2 val = __floats2half2_rn(s[pe][nc], s[pe + 1][nc]);
        *(__half2*)(outp + (size_t)(n0 + nc) * D_SZ + k0 + pe) = val;
    }
}

// ---------------------------------------------------------------------------
// Projection body (fp16 m16n8k16, ldmatrix): 128x128 tile, K-chunks of 64.
// 3-stage cp.async pipeline, one __syncthreads per chunk.
// ---------------------------------------------------------------------------
#define PROJH_SMEM (6 * 128 * KSTR * 2)
__device__ __forceinline__ void proj_body(int sel, int n0, int m0, const float* bias) {
    extern __shared__ char smc[];
    const int TB = 128 * KSTR * 2;
    __half* Xs = (__half*)smc;                    // 3 buffers
    __half* Ws = (__half*)(smc + 3 * TB);         // 3 buffers

    const int tid = threadIdx.x, lane = tid & 31, wid = tid >> 5;
    const int wm = wid >> 1, wn = wid & 1;
    const int g = lane >> 2, t = lane & 3;
    const __half* Xp = g_Xh;
    const __half* Wp = g_Wh + (size_t)sel * D_SZ * D_SZ;

    uint32_t xs_b = (uint32_t)__cvta_generic_to_shared(Xs);
    uint32_t ws_b = (uint32_t)__cvta_generic_to_shared(Ws);

    const int la = lane & 15, ha = lane >> 4;
    const int lbr = (lane & 7) + 8 * (lane >> 4);
    const int lbc = ((lane >> 3) & 1) * 8;
    uint32_t aoff[2], boff[4];
    #pragma unroll
    for (int mi = 0; mi < 2; mi++)
        aoff[mi] = ((wm * 32 + mi * 16 + la) * KSTR + 8 * ha) * 2;
    #pragma unroll
    for (int njp = 0; njp < 4; njp++)
        boff[njp] = ((wn * 64 + njp * 16 + lbr) * KSTR + lbc) * 2;

    auto issue = [&](int chunk, int buf) {
        int k0 = chunk * 64;
        #pragma unroll
        for (int i = tid; i < 1024; i += 256) {
            int r = i >> 3, c8 = (i & 7) << 3;
            cpa16(xs_b + buf * TB + (r * KSTR + c8) * 2, Xp + (size_t)(m0 + r) * D_SZ + k0 + c8);
        }
        #pragma unroll
        for (int i = tid; i < 1024; i += 256) {
            int r = i >> 3, c8 = (i & 7) << 3;
            cpa16(ws_b + buf * TB + (r * KSTR + c8) * 2, Wp + (size_t)(n0 + r) * D_SZ + k0 + c8);
        }
        cp_commit();
    };

    float acc[2][8][4] = {};
    issue(0, 0);
    issue(1, 1);

    for (int i = 0; i < 16; i++) {
        int buf = i % 3;
        if (i + 1 < 16) cp_wait<1>(); else cp_wait<0>();
        __syncthreads();                       // tile i ready; all done with buf (i+2)%3
        if (i + 2 < 16) issue(i + 2, (i + 2) % 3);

        #pragma unroll
        for (int k16 = 0; k16 < 4; k16++) {
            unsigned a[2][4], b[4][4];
            #pragma unroll
            for (int mi = 0; mi < 2; mi++)
                ldsm4(a[mi][0], a[mi][1], a[mi][2], a[mi][3],
                      xs_b + buf * TB + aoff[mi] + k16 * 32);
            #pragma unroll
            for (int njp = 0; njp < 4; njp++)
                ldsm4(b[njp][0], b[njp][1], b[njp][2], b[njp][3],
                      ws_b + buf * TB + boff[njp] + k16 * 32);
            #pragma unroll
            for (int mi = 0; mi < 2; mi++)
                #pragma unroll
                for (int nj = 0; nj < 8; nj++)
                    mma16h(acc[mi][nj], a[mi], &b[nj >> 1][2 * (nj & 1)]);
        }
    }

    #pragma unroll
    for (int mi = 0; mi < 2; mi++) {
        int row = m0 + wm * 32 + mi * 16 + g;
        int bb = row >> 11, s = row & (S_SZ - 1);
        #pragma unroll
        for (int nj = 0; nj < 8; nj++) {
            int col = n0 + wn * 64 + nj * 8 + 2 * t;
            int h = col >> 6, d = col & 63;
            float bs = (sel == 0) ? KLOG : 1.0f;
            float b0 = bias[col] * bs, b1 = bias[col + 1] * bs;
            float v0 = acc[mi][nj][0] + b0, v1 = acc[mi][nj][1] + b1;
            float v2 = acc[mi][nj][2] + b0, v3 = acc[mi][nj][3] + b1;
            size_t base0 = ((size_t)(bb * H_SZ + h) * S_SZ + s) * HD_SZ;
            size_t base1 = ((size_t)(bb * H_SZ + h) * S_SZ + s + 8) * HD_SZ;
            if (sel == 2) {
                *(float2*)(g_V + base0 + d) = make_float2(v0, v1);
                *(float2*)(g_V + base1 + d) = make_float2(v2, v3);
            } else {
                __half* hp = (sel == 0) ? g_Qh : g_Kh;
                *(__half2*)(hp + base0 + d) = __floats2half2_rn(v0, v1);
                *(__half2*)(hp + base1 + d) = __floats2half2_rn(v2, v3);
            }
        }
    }
}

__global__ __launch_bounds__(256, 2) void projqk(const float* __restrict__ bq,
                                                 const float* __restrict__ bk) {
    proj_body(blockIdx.z, blockIdx.x * 128, blockIdx.y * 128, blockIdx.z ? bk : bq);
}

// ---------------------------------------------------------------------------
// lse body: resident A = Q' (128 q-rows), streamed B = K (3-stage pipeline).
// ---------------------------------------------------------------------------
#define LSE_SMEM (4 * 128 * KSTR * 2 + 2 * 128 * 4)
__device__ __forceinline__ void lse_body(int bh, int q0) {
    extern __shared__ char smc[];
    const int TB = 128 * KSTR * 2;
    __half* Qs = (__half*)smc;                     // resident
    __half* Ks = (__half*)(smc + TB);              // 3 buffers
    float (*red)[128] = (float(*)[128])(smc + 4 * TB);

    const int tid = threadIdx.x, lane = tid & 31, wid = tid >> 5;
    const int wm = wid >> 1, wn = wid & 1;
    const int g = lane >> 2, t = lane & 3;
    const __half* Qp = g_Qh + (size_t)bh * S_SZ * HD_SZ;
    const __half* Kp = g_Kh + (size_t)bh * S_SZ * HD_SZ;

    uint32_t qs_b = (uint32_t)__cvta_generic_to_shared(Qs);
    uint32_t ks_b = (uint32_t)__cvta_generic_to_shared(Ks);

    const int la = lane & 15, ha = lane >> 4;
    const int lbr = (lane & 7) + 8 * (lane >> 4);
    const int lbc = ((lane >> 3) & 1) * 8;
    uint32_t aoff[2], boff[4];
    #pragma unroll
    for (int mi = 0; mi < 2; mi++)
        aoff[mi] = qs_b + ((wm * 32 + mi * 16 + la) * KSTR + 8 * ha) * 2;
    #pragma unroll
    for (int njp = 0; njp < 4; njp++)
        boff[njp] = ((wn * 64 + njp * 16 + lbr) * KSTR + lbc) * 2;

    #pragma unroll
    for (int i = tid; i < 1024; i += 256) {
        int r = i >> 3, c8 = (i & 7) << 3;
        cpa16(qs_b + (r * KSTR + c8) * 2, Qp + (size_t)(q0 + r) * HD_SZ + c8);
    }
    cp_commit();

    auto issue = [&](int ktile, int buf) {
        int n0 = ktile * 128;
        #pragma unroll
        for (int i = tid; i < 1024; i += 256) {
            int r = i >> 3, c8 = (i & 7) << 3;
            cpa16(ks_b + buf * TB + (r * KSTR + c8) * 2, Kp + (size_t)(n0 + r) * HD_SZ + c8);
        }
        cp_commit();
    };

    issue(0, 0);
    issue(1, 1);

    float rs[2][2] = {};
    const __half2 hz = __floats2half2_rn(0.f, 0.f);

    for (int i = 0; i < 16; i++) {
        int buf = i % 3;
        if (i + 1 < 16) cp_wait<1>(); else cp_wait<0>();
        __syncthreads();
        if (i + 2 < 16) issue(i + 2, (i + 2) % 3);

        float acc[2][8][4] = {};
        #pragma unroll
        for (int k16 = 0; k16 < 4; k16++) {
            unsigned a[2][4], b[4][4];
            #pragma unroll
            for (int mi = 0; mi < 2; mi++)
                ldsm4(a[mi][0], a[mi][1], a[mi][2], a[mi][3], aoff[mi] + k16 * 32);
            #pragma unroll
            for (int njp = 0; njp < 4; njp++)
                ldsm4(b[njp][0], b[njp][1], b[njp][2], b[njp][3],
                      ks_b + buf * TB + boff[njp] + k16 * 32);
            #pragma unroll
            for (int mi = 0; mi < 2; mi++)
                #pragma unroll
                for (int nj = 0; nj < 8; nj++)
                    mma16h(acc[mi][nj], a[mi], &b[nj >> 1][2 * (nj & 1)]);
        }

        // 8 independent exp/accumulate chains (length 4) per thread
        #pragma unroll
        for (int mi = 0; mi < 2; mi++) {
            __half2 e0 = hz, e1 = hz, e2 = hz, e3 = hz;
            #pragma unroll
            for (int nj = 0; nj < 8; nj += 2) {
                e0 = __hadd2(e0, h2ex2(__floats2half2_rn(acc[mi][nj][0],     acc[mi][nj][1])));
                e1 = __hadd2(e1, h2ex2(__floats2half2_rn(acc[mi][nj][2],     acc[mi][nj][3])));
                e2 = __hadd2(e2, h2ex2(__floats2half2_rn(acc[mi][nj + 1][0], acc[mi][nj + 1][1])));
                e3 = __hadd2(e3, h2ex2(__floats2half2_rn(acc[mi][nj + 1][2], acc[mi][nj + 1][3])));
            }
            float2 f0 = __half22float2(__hadd2(e0, e2));
            float2 f1 = __half22float2(__hadd2(e1, e3));
            rs[mi][0] += f0.x + f0.y;
            rs[mi][1] += f1.x + f1.y;
        }
    }

    #pragma unroll
    for (int mi = 0; mi < 2; mi++)
        #pragma unroll
        for (int h2 = 0; h2 < 2; h2++) {
            float v = rs[mi][h2];
            v += __shfl_xor_sync(0xffffffffu, v, 1);
            v += __shfl_xor_sync(0xffffffffu, v, 2);
            if (t == 0) red[wn][wm * 32 + mi * 16 + g + 8 * h2] = v;
        }
    __syncthreads();
    if (tid < 128)
        g_Ri[bh * S_SZ + q0 + tid] = 1.0f / (red[0][tid] + red[1][tid]);
}

// Fused launch: blocks [0,256) do the V projection, [256,768) do lse.
__global__ __launch_bounds__(256, 2) void vproj_lse(const float* __restrict__ bv) {
    if (blockIdx.x < 256) {
        proj_body(2, (blockIdx.x & 7) * 128, (blockIdx.x >> 3) * 128, bv);
    } else {
        int idx = blockIdx.x - 256;
        lse_body(idx >> 4, (idx & 15) * 128);
    }
}

// ---------------------------------------------------------------------------
// Pass B (wk): resident A = K (128 keys), streamed B = Q' + Ri (3-stage).
// ---------------------------------------------------------------------------
#define WK_SMEM (4 * 128 * KSTR * 2 + 3 * 128 * 4 + 2 * 128 * 4)
__global__ __launch_bounds__(256, 2) void wk_mma() {
    extern __shared__ char smc[];
    const int TB = 128 * KSTR * 2;
    __half* Kr = (__half*)smc;
    __half* Qs = (__half*)(smc + TB);              // 3 buffers
    float (*rsm)[128] = (float(*)[128])(smc + 4 * TB);            // 3 buffers
    float (*red)[128] = (float(*)[128])(smc + 4 * TB + 3 * 128 * 4);

    const int tid = threadIdx.x, lane = tid & 31, wid = tid >> 5;
    const int wm = wid >> 1, wn = wid & 1;
    const int g = lane >> 2, t = lane & 3;
    const int bh = blockIdx.y, k0 = blockIdx.x * 128;
    const __half* Qp = g_Qh + (size_t)bh * S_SZ * HD_SZ;
    const __half* Kp = g_Kh + (size_t)bh * S_SZ * HD_SZ;
    const float* Rp = g_Ri + bh * S_SZ;

    uint32_t kr_b = (uint32_t)__cvta_generic_to_shared(Kr);
    uint32_t qs_b = (uint32_t)__cvta_generic_to_shared(Qs);
    uint32_t rs_b = (uint32_t)__cvta_generic_to_shared(&rsm[0][0]);

    const int la = lane & 15, ha = lane >> 4;
    const int lbr = (lane & 7) + 8 * (lane >> 4);
    const int lbc = ((lane >> 3) & 1) * 8;
    uint32_t aoff[2], boff[4];
    #pragma unroll
    for (int mi = 0; mi < 2; mi++)
        aoff[mi] = kr_b + ((wm * 32 + mi * 16 + la) * KSTR + 8 * ha) * 2;
    #pragma unroll
    for (int njp = 0; njp < 4; njp++)
        boff[njp] = ((wn * 64 + njp * 16 + lbr) * KSTR + lbc) * 2;

    #pragma unroll
    for (int i = tid; i < 1024; i += 256) {
        int r = i >> 3, c8 = (i & 7) << 3;
        cpa16(kr_b + (r * KSTR + c8) * 2, Kp + (size_t)(k0 + r) * HD_SZ + c8);
    }
    cp_commit();

    auto issue = [&](int qtile, int buf) {
        int n0 = qtile * 128;
        #pragma unroll
        for (int i = tid; i < 1024; i += 256) {
            int r = i >> 3, c8 = (i & 7) << 3;
            cpa16(qs_b + buf * TB + (r * KSTR + c8) * 2, Qp + (size_t)(n0 + r) * HD_SZ + c8);
        }
        if (tid < 32) cpa16(rs_b + (buf * 128 + tid * 4) * 4, Rp + n0 + tid * 4);
        cp_commit();
    };

    issue(0, 0);
    issue(1, 1);

    float rs[2][2] = {};
    const __half2 hz = __floats2half2_rn(0.f, 0.f);

    for (int i = 0; i < 16; i++) {
        int buf = i % 3;
        if (i + 1 < 16) cp_wait<1>(); else cp_wait<0>();
        __syncthreads();
        if (i + 2 < 16) issue(i + 2, (i + 2) % 3);

        float acc[2][8][4] = {};
        #pragma unroll
        for (int k16 = 0; k16 < 4; k16++) {
            unsigned a[2][4], b[4][4];
            #pragma unroll
            for (int mi = 0; mi < 2; mi++)
                ldsm4(a[mi][0], a[mi][1], a[mi][2], a[mi][3], aoff[mi] + k16 * 32);
            #pragma unroll
            for (int njp = 0; njp < 4; njp++)
                ldsm4(b[njp][0], b[njp][1], b[njp][2], b[njp][3],
                      qs_b + buf * TB + boff[njp] + k16 * 32);
            #pragma unroll
            for (int mi = 0; mi < 2; mi++)
                #pragma unroll
                for (int nj = 0; nj < 8; nj++)
                    mma16h(acc[mi][nj], a[mi], &b[nj >> 1][2 * (nj & 1)]);
        }

        // 8 independent fma chains (length 4) per thread
        __half2 hacc[2][2][2];
        #pragma unroll
        for (int mi = 0; mi < 2; mi++)
            #pragma unroll
            for (int hh = 0; hh < 2; hh++)
                #pragma unroll
                for (int p = 0; p < 2; p++) hacc[mi][hh][p] = hz;
        #pragma unroll
        for (int nj = 0; nj < 8; nj += 2) {
            int cb0 = wn * 64 + nj * 8 + 2 * t;
            int cb1 = cb0 + 8;
            __half2 rr0 = __floats2half2_rn(rsm[buf][cb0], rsm[buf][cb0 + 1]);
            __half2 rr1 = __floats2half2_rn(rsm[buf][cb1], rsm[buf][cb1 + 1]);
            #pragma unroll
            for (int mi = 0; mi < 2; mi++) {
                hacc[mi][0][0] = __hfma2(h2ex2(__floats2half2_rn(acc[mi][nj][0],     acc[mi][nj][1])),     rr0, hacc[mi][0][0]);
                hacc[mi][1][0] = __hfma2(h2ex2(__floats2half2_rn(acc[mi][nj][2],     acc[mi][nj][3])),     rr0, hacc[mi][1][0]);
                hacc[mi][0][1] = __hfma2(h2ex2(__floats2half2_rn(acc[mi][nj + 1][0], acc[mi][nj + 1][1])), rr1, hacc[mi][0][1]);
                hacc[mi][1][1] = __hfma2(h2ex2(__floats2half2_rn(acc[mi][nj + 1][2], acc[mi][nj + 1][3])), rr1, hacc[mi][1][1]);
            }
        }
        #pragma unroll
        for (int mi = 0; mi < 2; mi++) {
            float2 f0 = __half22float2(__hadd2(hacc[mi][0][0], hacc[mi][0][1]));
            float2 f1 = __half22float2(__hadd2(hacc[mi][1][0], hacc[mi][1][1]));
            rs[mi][0] += f0.x + f0.y;
            rs[mi][1] += f1.x + f1.y;
        }
    }

    #pragma unroll
    for (int mi = 0; mi < 2; mi++)
        #pragma unroll
        for (int h2 = 0; h2 < 2; h2++) {
            float v = rs[mi][h2];
            v += __shfl_xor_sync(0xffffffffu, v, 1);
            v += __shfl_xor_sync(0xffffffffu, v, 2);
            if (t == 0) red[wn][wm * 32 + mi * 16 + g + 8 * h2] = v;
        }
    __syncthreads();
    if (tid < 128)
        g_w[bh * S_SZ + k0 + tid] = (red[0][tid] + red[1][tid]) * (1.0f / S_SZ);
}

// ---------------------------------------------------------------------------
// Output: out[b, h*64+d] = sum_k w[bh,k] * V[bh,k,d]. One block per bh.
// ---------------------------------------------------------------------------
__global__ __launch_bounds__(256) void outk(float* __restrict__ out) {
    __shared__ float red2[4][64];
    const int bh = blockIdx.x, tid = threadIdx.x;
    const int d = tid & 63, sl = tid >> 6;
    const float* Vp = g_V + (size_t)bh * S_SZ * HD_SZ;
    const float* wp = g_w + bh * S_SZ;
    float a = 0.f;
    #pragma unroll 4
    for (int k = sl * 512; k < (sl + 1) * 512; ++k)
        a = fmaf(wp[k], Vp[(size_t)k * HD_SZ + d], a);
    red2[sl][d] = a;
    __syncthreads();
    if (tid < 64) {
        float s = red2[0][tid] + red2[1][tid] + red2[2][tid] + red2[3][tid];
        int bb = bh >> 4, h = bh & 15;
        out[bb * D_SZ + h * HD_SZ + tid] = s;
    }
}

// ---------------------------------------------------------------------------
extern "C" void kernel_launch(void* const* d_in, const int* in_sizes, int n_in,
                              void* d_out, int out_size) {
    (void)in_sizes; (void)n_in; (void)out_size;
    const float* X  = (const float*)d_in[0];
    const float* Wq = (const float*)d_in[1];
    const float* bq = (const float*)d_in[2];
    const float* Wk = (const float*)d_in[3];
    const float* bk = (const float*)d_in[4];
    const float* Wv = (const float*)d_in[5];
    const float* bv = (const float*)d_in[6];
    float* out = (float*)d_out;

    cudaFuncSetAttribute(projqk,    cudaFuncAttributeMaxDynamicSharedMemorySize, PROJH_SMEM);
    cudaFuncSetAttribute(vproj_lse, cudaFuncAttributeMaxDynamicSharedMemorySize, PROJH_SMEM);
    cudaFuncSetAttribute(wk_mma,    cudaFuncAttributeMaxDynamicSharedMemorySize, WK_SMEM);

    prep_all<<<4096, 256>>>(X, Wq, Wk, Wv);

    dim3 gqk(D_SZ / 128, TOK_SZ / 128, 2);     // (8, 32, 2)
    projqk<<<gqk, 256, PROJH_SMEM>>>(bq, bk);

    vproj_lse<<<768, 256, PROJH_SMEM>>>(bv);   // 256 V-proj blocks + 512 lse blocks

    dim3 ga(S_SZ / 128, BH_SZ);                // (16, 32)
    wk_mma<<<ga, 256, WK_SMEM>>>();

    outk<<<BH_SZ, 256>>>(out);
}

// round 15
// speedup vs baseline: 1.0252x; 1.0252x over previous
#include <cuda_runtime.h>
#include <cuda_fp16.h>
#include <cstdint>

#define S_SZ 2048
#define D_SZ 1024
#define H_SZ 16
#define HD_SZ 64
#define B_SZ 2
#define BH_SZ (B_SZ * H_SZ)       // 32
#define TOK_SZ (B_SZ * S_SZ)      // 4096
#define KLOG 0.18033688011112042f // 0.125 * log2(e)
#define KSTR 72                   // halves per smem row (144B: LDSM conflict-free)

// Scratch (device globals: allocation-free rule)
__device__ __half g_Xh[TOK_SZ * D_SZ];        // fp16 X, natural order
__device__ __half g_Wh[3 * D_SZ * D_SZ];      // fp16 W^T [n][k]; Wq pre-scaled by KLOG
__device__ __half g_Qh[BH_SZ * S_SZ * HD_SZ]; // fp16 Q (KLOG-scaled), natural d
__device__ __half g_Kh[BH_SZ * S_SZ * HD_SZ]; // fp16 K, natural d
__device__ float  g_V[BH_SZ * S_SZ * HD_SZ];  // full fp32
__device__ float  g_Ri[BH_SZ * S_SZ];         // 1 / rowsum(exp2(scores2))
__device__ float  g_w[BH_SZ * S_SZ];          // mean attention weight per key

// ---------------------------------------------------------------------------
__device__ __forceinline__ void mma16h(float c[4], const unsigned a[4], const unsigned* b) {
    asm volatile(
        "mma.sync.aligned.m16n8k16.row.col.f32.f16.f16.f32 "
        "{%0,%1,%2,%3}, {%4,%5,%6,%7}, {%8,%9}, {%0,%1,%2,%3};\n"
        : "+f"(c[0]), "+f"(c[1]), "+f"(c[2]), "+f"(c[3])
        : "r"(a[0]), "r"(a[1]), "r"(a[2]), "r"(a[3]), "r"(b[0]), "r"(b[1]));
}

__device__ __forceinline__ void ldsm4(unsigned& r0, unsigned& r1, unsigned& r2, unsigned& r3,
                                      uint32_t addr) {
    asm volatile("ldmatrix.sync.aligned.m8n8.x4.shared.b16 {%0,%1,%2,%3}, [%4];"
                 : "=r"(r0), "=r"(r1), "=r"(r2), "=r"(r3) : "r"(addr));
}

// two exp2 per MUFU op
__device__ __forceinline__ __half2 h2ex2(__half2 x) {
    unsigned xi = *reinterpret_cast<unsigned*>(&x), yi;
    asm("ex2.approx.f16x2 %0, %1;" : "=r"(yi) : "r"(xi));
    return *reinterpret_cast<__half2*>(&yi);
}

__device__ __forceinline__ void cpa16(uint32_t dst, const void* src) {
    asm volatile("cp.async.ca.shared.global [%0], [%1], 16;\n" :: "r"(dst), "l"(src));
}
__device__ __forceinline__ void cp_commit() { asm volatile("cp.async.commit_group;\n"); }
template <int N> __device__ __forceinline__ void cp_wait() {
    asm volatile("cp.async.wait_group %0;\n" :: "n"(N));
}

// ---------------------------------------------------------------------------
// Prep (fused): blocks [0,1024) convert X to fp16; blocks [1024,4096) build
// fp16 W^T with KLOG folded into Wq.
// ---------------------------------------------------------------------------
__global__ __launch_bounds__(256) void prep_all(const float* __restrict__ X,
                                                const float* __restrict__ Wq,
                                                const float* __restrict__ Wk,
                                                const float* __restrict__ Wv) {
    __shared__ float s[32][33];
    const int bx = blockIdx.x, tid = threadIdx.x;
    if (bx < 1024) {
        const int N8 = TOK_SZ * D_SZ / 8;
        for (int i = bx * 256 + tid; i < N8; i += 1024 * 256) {
            float4 v0 = ((const float4*)X)[2 * i];
            float4 v1 = ((const float4*)X)[2 * i + 1];
            __half2 h[4] = { __floats2half2_rn(v0.x, v0.y), __floats2half2_rn(v0.z, v0.w),
                             __floats2half2_rn(v1.x, v1.y), __floats2half2_rn(v1.z, v1.w) };
            *(uint4*)(g_Xh + (size_t)8 * i) = *(const uint4*)h;
        }
        return;
    }
    const int idx = bx - 1024;
    const int sel = idx >> 10, rem = idx & 1023;
    const int k0 = (rem & 31) * 32, n0 = (rem >> 5) * 32;
    const float* Wp = (sel == 0) ? Wq : (sel == 1) ? Wk : Wv;
    const float scale = (sel == 0) ? KLOG : 1.0f;
    const int tx = tid & 31, ty = tid >> 5;

    #pragma unroll
    for (int j = 0; j < 4; j++) {
        int kr = ty + j * 8;
        s[kr][tx] = Wp[(size_t)(k0 + kr) * D_SZ + n0 + tx] * scale;
    }
    __syncthreads();

    __half* outp = g_Wh + (size_t)sel * D_SZ * D_SZ;
    #pragma unroll
    for (int j = 0; j < 2; j++) {
        int i2 = tid + 256 * j;
        int nc = i2 >> 4, pe = (i2 & 15) << 1;
        __half2 val = __floats2half2_rn(s[pe][nc], s[pe + 1][nc]);
        *(__half2*)(outp + (size_t)(n0 + nc) * D_SZ + k0 + pe) = val;
    }
}

// ---------------------------------------------------------------------------
// Projection body (fp16 m16n8k16, ldmatrix): 128x128 tile, K-chunks of 64,
// 2-stage cp.async double buffering (R12-proven structure).
// ---------------------------------------------------------------------------
#define PROJH_SMEM (4 * 128 * KSTR * 2)
__device__ __forceinline__ void proj_body(int sel, int n0, int m0, const float* bias) {
    extern __shared__ char smc[];
    const int TB = 128 * KSTR * 2;
    __half* Xs = (__half*)smc;
    __half* Ws = (__half*)(smc + 2 * TB);

    const int tid = threadIdx.x, lane = tid & 31, wid = tid >> 5;
    const int wm = wid >> 1, wn = wid & 1;
    const int g = lane >> 2, t = lane & 3;
    const __half* Xp = g_Xh;
    const __half* Wp = g_Wh + (size_t)sel * D_SZ * D_SZ;

    uint32_t xs_b = (uint32_t)__cvta_generic_to_shared(Xs);
    uint32_t ws_b = (uint32_t)__cvta_generic_to_shared(Ws);

    const int la = lane & 15, ha = lane >> 4;
    const int lbr = (lane & 7) + 8 * (lane >> 4);
    const int lbc = ((lane >> 3) & 1) * 8;
    uint32_t aoff[2], boff[4];
    #pragma unroll
    for (int mi = 0; mi < 2; mi++)
        aoff[mi] = ((wm * 32 + mi * 16 + la) * KSTR + 8 * ha) * 2;
    #pragma unroll
    for (int njp = 0; njp < 4; njp++)
        boff[njp] = ((wn * 64 + njp * 16 + lbr) * KSTR + lbc) * 2;

    auto issue = [&](int chunk, int buf) {
        int k0 = chunk * 64;
        #pragma unroll
        for (int i = tid; i < 1024; i += 256) {
            int r = i >> 3, c8 = (i & 7) << 3;
            cpa16(xs_b + buf * TB + (r * KSTR + c8) * 2, Xp + (size_t)(m0 + r) * D_SZ + k0 + c8);
        }
        #pragma unroll
        for (int i = tid; i < 1024; i += 256) {
            int r = i >> 3, c8 = (i & 7) << 3;
            cpa16(ws_b + buf * TB + (r * KSTR + c8) * 2, Wp + (size_t)(n0 + r) * D_SZ + k0 + c8);
        }
        cp_commit();
    };

    float acc[2][8][4] = {};
    issue(0, 0);

    for (int i = 0; i < 16; i++) {
        int buf = i & 1;
        if (i + 1 < 16) { issue(i + 1, 1 - buf); cp_wait<1>(); }
        else cp_wait<0>();
        __syncthreads();

        #pragma unroll
        for (int k16 = 0; k16 < 4; k16++) {
            unsigned a[2][4], b[4][4];
            #pragma unroll
            for (int mi = 0; mi < 2; mi++)
                ldsm4(a[mi][0], a[mi][1], a[mi][2], a[mi][3],
                      xs_b + buf * TB + aoff[mi] + k16 * 32);
            #pragma unroll
            for (int njp = 0; njp < 4; njp++)
                ldsm4(b[njp][0], b[njp][1], b[njp][2], b[njp][3],
                      ws_b + buf * TB + boff[njp] + k16 * 32);
            #pragma unroll
            for (int mi = 0; mi < 2; mi++)
                #pragma unroll
                for (int nj = 0; nj < 8; nj++)
                    mma16h(acc[mi][nj], a[mi], &b[nj >> 1][2 * (nj & 1)]);
        }
        __syncthreads();
    }

    #pragma unroll
    for (int mi = 0; mi < 2; mi++) {
        int row = m0 + wm * 32 + mi * 16 + g;
        int bb = row >> 11, s = row & (S_SZ - 1);
        #pragma unroll
        for (int nj = 0; nj < 8; nj++) {
            int col = n0 + wn * 64 + nj * 8 + 2 * t;
            int h = col >> 6, d = col & 63;
            float bs = (sel == 0) ? KLOG : 1.0f;
            float b0 = bias[col] * bs, b1 = bias[col + 1] * bs;
            float v0 = acc[mi][nj][0] + b0, v1 = acc[mi][nj][1] + b1;
            float v2 = acc[mi][nj][2] + b0, v3 = acc[mi][nj][3] + b1;
            size_t base0 = ((size_t)(bb * H_SZ + h) * S_SZ + s) * HD_SZ;
            size_t base1 = ((size_t)(bb * H_SZ + h) * S_SZ + s + 8) * HD_SZ;
            if (sel == 2) {
                *(float2*)(g_V + base0 + d) = make_float2(v0, v1);
                *(float2*)(g_V + base1 + d) = make_float2(v2, v3);
            } else {
                __half* hp = (sel == 0) ? g_Qh : g_Kh;
                *(__half2*)(hp + base0 + d) = __floats2half2_rn(v0, v1);
                *(__half2*)(hp + base1 + d) = __floats2half2_rn(v2, v3);
            }
        }
    }
}

__global__ __launch_bounds__(256, 2) void projqk(const float* __restrict__ bq,
                                                 const float* __restrict__ bk) {
    proj_body(blockIdx.z, blockIdx.x * 128, blockIdx.y * 128, blockIdx.z ? bk : bq);
}

// ---------------------------------------------------------------------------
// lse body: resident A = Q' (128 q-rows), streamed B = K in 256-row tiles,
// each processed as two 128-row halves (half the barriers/cp groups of R12).
// ---------------------------------------------------------------------------
#define TBH (128 * KSTR * 2)      // bytes per 128-row half
#define TBS (256 * KSTR * 2)      // bytes per 256-row streamed tile
#define LSE_SMEM (TBH + 2 * TBS + 2 * 128 * 4)
__device__ __forceinline__ void lse_body(int bh, int q0) {
    extern __shared__ char smc[];
    __half* Qs = (__half*)smc;                     // resident 128 rows
    __half* Ks = (__half*)(smc + TBH);             // 2 buffers x 256 rows
    float (*red)[128] = (float(*)[128])(smc + TBH + 2 * TBS);

    const int tid = threadIdx.x, lane = tid & 31, wid = tid >> 5;
    const int wm = wid >> 1, wn = wid & 1;
    const int g = lane >> 2, t = lane & 3;
    const __half* Qp = g_Qh + (size_t)bh * S_SZ * HD_SZ;
    const __half* Kp = g_Kh + (size_t)bh * S_SZ * HD_SZ;

    uint32_t qs_b = (uint32_t)__cvta_generic_to_shared(Qs);
    uint32_t ks_b = (uint32_t)__cvta_generic_to_shared(Ks);

    const int la = lane & 15, ha = lane >> 4;
    const int lbr = (lane & 7) + 8 * (lane >> 4);
    const int lbc = ((lane >> 3) & 1) * 8;
    uint32_t aoff[2], boff[4];
    #pragma unroll
    for (int mi = 0; mi < 2; mi++)
        aoff[mi] = qs_b + ((wm * 32 + mi * 16 + la) * KSTR + 8 * ha) * 2;
    #pragma unroll
    for (int njp = 0; njp < 4; njp++)
        boff[njp] = ((wn * 64 + njp * 16 + lbr) * KSTR + lbc) * 2;

    #pragma unroll
    for (int i = tid; i < 1024; i += 256) {
        int r = i >> 3, c8 = (i & 7) << 3;
        cpa16(qs_b + (r * KSTR + c8) * 2, Qp + (size_t)(q0 + r) * HD_SZ + c8);
    }
    cp_commit();

    auto issue = [&](int ktile, int buf) {       // loads 256 rows
        int n0 = ktile * 256;
        #pragma unroll
        for (int i = tid; i < 2048; i += 256) {
            int r = i >> 3, c8 = (i & 7) << 3;
            cpa16(ks_b + buf * TBS + (r * KSTR + c8) * 2, Kp + (size_t)(n0 + r) * HD_SZ + c8);
        }
        cp_commit();
    };

    issue(0, 0);

    float rs[2][2] = {};

    for (int i = 0; i < 8; i++) {
        int buf = i & 1;
        if (i + 1 < 8) { issue(i + 1, 1 - buf); cp_wait<1>(); }
        else cp_wait<0>();
        __syncthreads();

        #pragma unroll
        for (int hh = 0; hh < 2; hh++) {         // two 128-row halves
            uint32_t hbase = ks_b + buf * TBS + hh * TBH;
            float acc[2][8][4] = {};
            #pragma unroll
            for (int k16 = 0; k16 < 4; k16++) {
                unsigned a[2][4], b[4][4];
                #pragma unroll
                for (int mi = 0; mi < 2; mi++)
                    ldsm4(a[mi][0], a[mi][1], a[mi][2], a[mi][3], aoff[mi] + k16 * 32);
                #pragma unroll
                for (int njp = 0; njp < 4; njp++)
                    ldsm4(b[njp][0], b[njp][1], b[njp][2], b[njp][3],
                          hbase + boff[njp] + k16 * 32);
                #pragma unroll
                for (int mi = 0; mi < 2; mi++)
                    #pragma unroll
                    for (int nj = 0; nj < 8; nj++)
                        mma16h(acc[mi][nj], a[mi], &b[nj >> 1][2 * (nj & 1)]);
            }

            #pragma unroll
            for (int mi = 0; mi < 2; mi++) {
                __half2 hg = __floats2half2_rn(0.f, 0.f), hg8 = hg;
                #pragma unroll
                for (int nj = 0; nj < 8; nj++) {
                    hg  = __hadd2(hg,  h2ex2(__floats2half2_rn(acc[mi][nj][0], acc[mi][nj][1])));
                    hg8 = __hadd2(hg8, h2ex2(__floats2half2_rn(acc[mi][nj][2], acc[mi][nj][3])));
                }
                float2 f0 = __half22float2(hg), f1 = __half22float2(hg8);
                rs[mi][0] += f0.x + f0.y;
                rs[mi][1] += f1.x + f1.y;
            }
        }
        __syncthreads();
    }

    #pragma unroll
    for (int mi = 0; mi < 2; mi++)
        #pragma unroll
        for (int h2 = 0; h2 < 2; h2++) {
            float v = rs[mi][h2];
            v += __shfl_xor_sync(0xffffffffu, v, 1);
            v += __shfl_xor_sync(0xffffffffu, v, 2);
            if (t == 0) red[wn][wm * 32 + mi * 16 + g + 8 * h2] = v;
        }
    __syncthreads();
    if (tid < 128)
        g_Ri[bh * S_SZ + q0 + tid] = 1.0f / (red[0][tid] + red[1][tid]);
}

// Fused launch: blocks [0,256) do the V projection, [256,768) do lse.
__global__ __launch_bounds__(256, 2) void vproj_lse(const float* __restrict__ bv) {
    if (blockIdx.x < 256) {
        proj_body(2, (blockIdx.x & 7) * 128, (blockIdx.x >> 3) * 128, bv);
    } else {
        int idx = blockIdx.x - 256;
        lse_body(idx >> 4, (idx & 15) * 128);
    }
}

// ---------------------------------------------------------------------------
// Pass B (wk): resident A = K (128 keys), streamed B = Q' + Ri (256-row tiles).
// ---------------------------------------------------------------------------
#define WK_SMEM (TBH + 2 * TBS + 2 * 256 * 4 + 2 * 128 * 4)
__global__ __launch_bounds__(256, 2) void wk_mma() {
    extern __shared__ char smc[];
    __half* Kr = (__half*)smc;
    __half* Qs = (__half*)(smc + TBH);             // 2 buffers x 256 rows
    float (*rsm)[256] = (float(*)[256])(smc + TBH + 2 * TBS);     // 2 x 256
    float (*red)[128] = (float(*)[128])(smc + TBH + 2 * TBS + 2 * 256 * 4);

    const int tid = threadIdx.x, lane = tid & 31, wid = tid >> 5;
    const int wm = wid >> 1, wn = wid & 1;
    const int g = lane >> 2, t = lane & 3;
    const int bh = blockIdx.y, k0 = blockIdx.x * 128;
    const __half* Qp = g_Qh + (size_t)bh * S_SZ * HD_SZ;
    const __half* Kp = g_Kh + (size_t)bh * S_SZ * HD_SZ;
    const float* Rp = g_Ri + bh * S_SZ;

    uint32_t kr_b = (uint32_t)__cvta_generic_to_shared(Kr);
    uint32_t qs_b = (uint32_t)__cvta_generic_to_shared(Qs);
    uint32_t rs_b = (uint32_t)__cvta_generic_to_shared(&rsm[0][0]);

    const int la = lane & 15, ha = lane >> 4;
    const int lbr = (lane & 7) + 8 * (lane >> 4);
    const int lbc = ((lane >> 3) & 1) * 8;
    uint32_t aoff[2], boff[4];
    #pragma unroll
    for (int mi = 0; mi < 2; mi++)
        aoff[mi] = kr_b + ((wm * 32 + mi * 16 + la) * KSTR + 8 * ha) * 2;
    #pragma unroll
    for (int njp = 0; njp < 4; njp++)
        boff[njp] = ((wn * 64 + njp * 16 + lbr) * KSTR + lbc) * 2;

    #pragma unroll
    for (int i = tid; i < 1024; i += 256) {
        int r = i >> 3, c8 = (i & 7) << 3;
        cpa16(kr_b + (r * KSTR + c8) * 2, Kp + (size_t)(k0 + r) * HD_SZ + c8);
    }
    cp_commit();

    auto issue = [&](int qtile, int buf) {       // loads 256 q rows + 256 Ri
        int n0 = qtile * 256;
        #pragma unroll
        for (int i = tid; i < 2048; i += 256) {
            int r = i >> 3, c8 = (i & 7) << 3;
            cpa16(qs_b + buf * TBS + (r * KSTR + c8) * 2, Qp + (size_t)(n0 + r) * HD_SZ + c8);
        }
        if (tid < 64) cpa16(rs_b + (buf * 256 + tid * 4) * 4, Rp + n0 + tid * 4);
        cp_commit();
    };

    issue(0, 0);

    float rs[2][2] = {};

    for (int i = 0; i < 8; i++) {
        int buf = i & 1;
        if (i + 1 < 8) { issue(i + 1, 1 - buf); cp_wait<1>(); }
        else cp_wait<0>();
        __syncthreads();

        #pragma unroll
        for (int hh = 0; hh < 2; hh++) {
            uint32_t hbase = qs_b + buf * TBS + hh * TBH;
            float acc[2][8][4] = {};
            #pragma unroll
            for (int k16 = 0; k16 < 4; k16++) {
                unsigned a[2][4], b[4][4];
                #pragma unroll
                for (int mi = 0; mi < 2; mi++)
                    ldsm4(a[mi][0], a[mi][1], a[mi][2], a[mi][3], aoff[mi] + k16 * 32);
                #pragma unroll
                for (int njp = 0; njp < 4; njp++)
                    ldsm4(b[njp][0], b[njp][1], b[njp][2], b[njp][3],
                          hbase + boff[njp] + k16 * 32);
                #pragma unroll
                for (int mi = 0; mi < 2; mi++)
                    #pragma unroll
                    for (int nj = 0; nj < 8; nj++)
                        mma16h(acc[mi][nj], a[mi], &b[nj >> 1][2 * (nj & 1)]);
            }

            __half2 hacc[2][2];
            hacc[0][0] = hacc[0][1] = hacc[1][0] = hacc[1][1] = __floats2half2_rn(0.f, 0.f);
            #pragma unroll
            for (int nj = 0; nj < 8; nj++) {
                int cb = hh * 128 + wn * 64 + nj * 8 + 2 * t;
                __half2 rr = __floats2half2_rn(rsm[buf][cb], rsm[buf][cb + 1]);
                #pragma unroll
                for (int mi = 0; mi < 2; mi++) {
                    hacc[mi][0] = __hfma2(h2ex2(__floats2half2_rn(acc[mi][nj][0], acc[mi][nj][1])), rr, hacc[mi][0]);
                    hacc[mi][1] = __hfma2(h2ex2(__floats2half2_rn(acc[mi][nj][2], acc[mi][nj][3])), rr, hacc[mi][1]);
                }
            }
            #pragma unroll
            for (int mi = 0; mi < 2; mi++) {
                float2 f0 = __half22float2(hacc[mi][0]), f1 = __half22float2(hacc[mi][1]);
                rs[mi][0] += f0.x + f0.y;
                rs[mi][1] += f1.x + f1.y;
            }
        }
        __syncthreads();
    }

    #pragma unroll
    for (int mi = 0; mi < 2; mi++)
        #pragma unroll
        for (int h2 = 0; h2 < 2; h2++) {
            float v = rs[mi][h2];
            v += __shfl_xor_sync(0xffffffffu, v, 1);
            v += __shfl_xor_sync(0xffffffffu, v, 2);
            if (t == 0) red[wn][wm * 32 + mi * 16 + g + 8 * h2] = v;
        }
    __syncthreads();
    if (tid < 128)
        g_w[bh * S_SZ + k0 + tid] = (red[0][tid] + red[1][tid]) * (1.0f / S_SZ);
}

// ---------------------------------------------------------------------------
// Output: out[b, h*64+d] = sum_k w[bh,k] * V[bh,k,d]. One block per bh.
// ---------------------------------------------------------------------------
__global__ __launch_bounds__(256) void outk(float* __restrict__ out) {
    __shared__ float red2[4][64];
    const int bh = blockIdx.x, tid = threadIdx.x;
    const int d = tid & 63, sl = tid >> 6;
    const float* Vp = g_V + (size_t)bh * S_SZ * HD_SZ;
    const float* wp = g_w + bh * S_SZ;
    float a = 0.f;
    #pragma unroll 4
    for (int k = sl * 512; k < (sl + 1) * 512; ++k)
        a = fmaf(wp[k], Vp[(size_t)k * HD_SZ + d], a);
    red2[sl][d] = a;
    __syncthreads();
    if (tid < 64) {
        float s = red2[0][tid] + red2[1][tid] + red2[2][tid] + red2[3][tid];
        int bb = bh >> 4, h = bh & 15;
        out[bb * D_SZ + h * HD_SZ + tid] = s;
    }
}

// ---------------------------------------------------------------------------
extern "C" void kernel_launch(void* const* d_in, const int* in_sizes, int n_in,
                              void* d_out, int out_size) {
    (void)in_sizes; (void)n_in; (void)out_size;
    const float* X  = (const float*)d_in[0];
    const float* Wq = (const float*)d_in[1];
    const float* bq = (const float*)d_in[2];
    const float* Wk = (const float*)d_in[3];
    const float* bk = (const float*)d_in[4];
    const float* Wv = (const float*)d_in[5];
    const float* bv = (const float*)d_in[6];
    float* out = (float*)d_out;

    cudaFuncSetAttribute(projqk,    cudaFuncAttributeMaxDynamicSharedMemorySize, PROJH_SMEM);
    cudaFuncSetAttribute(vproj_lse, cudaFuncAttributeMaxDynamicSharedMemorySize, LSE_SMEM);
    cudaFuncSetAttribute(wk_mma,    cudaFuncAttributeMaxDynamicSharedMemorySize, WK_SMEM);

    prep_all<<<4096, 256>>>(X, Wq, Wk, Wv);

    dim3 gqk(D_SZ / 128, TOK_SZ / 128, 2);     // (8, 32, 2)
    projqk<<<gqk, 256, PROJH_SMEM>>>(bq, bk);

    vproj_lse<<<768, 256, LSE_SMEM>>>(bv);     // 256 V-proj blocks + 512 lse blocks

    dim3 ga(S_SZ / 128, BH_SZ);                // (16, 32)
    wk_mma<<<ga, 256, WK_SMEM>>>();

    outk<<<BH_SZ, 256>>>(out);
}